// round 14
// baseline (speedup 1.0000x reference)
#include <cuda_runtime.h>
#include <math.h>

// Problem constants: N_OBJ=1024, C_DET=8, C_SEG=4, H=W=28
#define C_DET 8
#define C_SEG 4
#define HW4 196          // 28*28/4 (float4 units)
#define N_OBJ 1024
#define NB 8             // objects per block (one per warp)
#define NCHUNK (N_OBJ / NB)   // 128
#define RTHREADS 256
#define NITER 7          // ceil(196/32)
#define MAX_EDGES 64

// Global double accumulators: [c][0]=denom, [c][1..4]=A[c][s].
// Zero at module load; finalize re-zeroes after reading -> replay-safe.
__device__ double g_acc[C_DET][5];

__device__ __forceinline__ float4 ld4(const float4* p) { return *p; }

// Software-pipelined streaming scan. Warp=object; iteration i+1's 5 loads
// are issued BEFORE iteration i's FMAs consume the current batch, so each
// thread keeps >=10 independent LDG.128 in flight (latency-bound fix:
// R8 profile showed DRAM=41%, issue=10% -> long-scoreboard stalls).
__global__ __launch_bounds__(RTHREADS) void reduce_kernel(
    const float4* __restrict__ det4,   // (N,C_DET,HW4) float4
    const float4* __restrict__ seg4)   // (N,C_DET,C_SEG,HW4) float4
{
    const int c   = blockIdx.y;
    const int wid = threadIdx.x >> 5;
    const int lid = threadIdx.x & 31;
    const int n   = blockIdx.x * NB + wid;

    const size_t mb = (size_t)n * C_DET + c;
    const float4* __restrict__ dp = det4 + mb * HW4;
    const float4* __restrict__ sp = seg4 + mb * (C_SEG * HW4);

    float dsum = 0.0f;
    float a0 = 0.0f, a1 = 0.0f, a2 = 0.0f, a3 = 0.0f;

    // Prologue: issue iteration 0's loads.
    float4 d  = ld4(dp + lid);
    float4 s0 = ld4(sp + 0 * HW4 + lid);
    float4 s1 = ld4(sp + 1 * HW4 + lid);
    float4 s2 = ld4(sp + 2 * HW4 + lid);
    float4 s3 = ld4(sp + 3 * HW4 + lid);

    #pragma unroll
    for (int it = 0; it < NITER; it++) {
        float4 dn, t0, t1, t2, t3;
        if (it + 1 < NITER) {
            const int qn = lid + (it + 1) * 32;
            const bool ok = (qn < HW4);
            // Predicated prefetch of the next batch (issued before the FMAs
            // below consume the current batch -> 10 loads in flight).
            if (ok) {
                dn = ld4(dp + qn);
                t0 = ld4(sp + 0 * HW4 + qn);
                t1 = ld4(sp + 1 * HW4 + qn);
                t2 = ld4(sp + 2 * HW4 + qn);
                t3 = ld4(sp + 3 * HW4 + qn);
            } else {
                dn = make_float4(0.f, 0.f, 0.f, 0.f);
                t0 = t1 = t2 = t3 = make_float4(0.f, 0.f, 0.f, 0.f);
            }
        }

        if (lid + it * 32 < HW4) {
            dsum += (d.x + d.y) + (d.z + d.w);
            a0 += d.x * s0.x + d.y * s0.y + d.z * s0.z + d.w * s0.w;
            a1 += d.x * s1.x + d.y * s1.y + d.z * s1.z + d.w * s1.w;
            a2 += d.x * s2.x + d.y * s2.y + d.z * s2.z + d.w * s2.w;
            a3 += d.x * s3.x + d.y * s3.y + d.z * s3.z + d.w * s3.w;
        }

        if (it + 1 < NITER) { d = dn; s0 = t0; s1 = t1; s2 = t2; s3 = t3; }
    }

    // Warp reduce 5 scalars
    #pragma unroll
    for (int off = 16; off; off >>= 1) {
        dsum += __shfl_xor_sync(0xFFFFFFFFu, dsum, off);
        a0   += __shfl_xor_sync(0xFFFFFFFFu, a0, off);
        a1   += __shfl_xor_sync(0xFFFFFFFFu, a1, off);
        a2   += __shfl_xor_sync(0xFFFFFFFFu, a2, off);
        a3   += __shfl_xor_sync(0xFFFFFFFFu, a3, off);
    }

    __shared__ float sm[5][RTHREADS / 32];
    if (lid == 0) {
        sm[0][wid] = dsum; sm[1][wid] = a0; sm[2][wid] = a1;
        sm[3][wid] = a2;   sm[4][wid] = a3;
    }
    __syncthreads();

    if (threadIdx.x < 5) {              // 5 double atomics per block, 40 targets
        const int k = threadIdx.x;
        float r = 0.0f;
        #pragma unroll
        for (int w = 0; w < RTHREADS / 32; w++) r += sm[k][w];
        atomicAdd(&g_acc[c][k], (double)r);
    }
}

// Minimal finalize: parallel loads (edges, accumulators, dcp) in one latency
// round; deterministic fixed-order edge-weight build; self-zeroes g_acc.
__global__ __launch_bounds__(N_OBJ) void finalize_kernel(
    const float* __restrict__ dcp,       // (N_OBJ, C_DET)
    const int* __restrict__ edge_i,      // int32
    const int* __restrict__ edge_j,
    int n_edges,
    float* __restrict__ out)
{
    __shared__ double s_acc[C_DET][5];
    __shared__ float  s_w[C_DET];
    __shared__ float  red[N_OBJ / 32];
    __shared__ int    s_ei[MAX_EDGES], s_ej[MAX_EDGES];
    const int t = threadIdx.x;
    const int lid = t & 31;

    if (t < n_edges) { s_ei[t] = edge_i[t]; s_ej[t] = edge_j[t]; }
    if (t < C_DET * 5) ((double*)s_acc)[t] = ((const double*)g_acc)[t];

    const float4* dcp4 = (const float4*)dcp;
    const float4 d0 = dcp4[t * 2 + 0];
    const float4 d1 = dcp4[t * 2 + 1];
    __syncthreads();

    // Re-zero accumulators for the next replay (after everyone read them).
    if (t < C_DET * 5) ((double*)g_acc)[t] = 0.0;

    // Edge weights (deterministic fixed-order scan, atomic-free).
    if (t < C_DET) {
        double acc = 0.0;
        for (int e = 0; e < n_edges; e++)
            if (s_ej[e] == t)
                acc += s_acc[t][1 + s_ei[e]] / s_acc[t][0];
        s_w[t] = (float)acc;
    }
    __syncthreads();

    // Per-object prob + BCE mean (one object per thread).
    float w[C_DET];
    #pragma unroll
    for (int k = 0; k < C_DET; k++) w[k] = s_w[k];

    float p = d0.x * w[0] + d0.y * w[1] + d0.z * w[2] + d0.w * w[3]
            + d1.x * w[4] + d1.y * w[5] + d1.z * w[6] + d1.w * w[7];
    float l = -fmaxf(logf(p), -100.0f);

    #pragma unroll
    for (int off = 16; off; off >>= 1) l += __shfl_xor_sync(0xFFFFFFFFu, l, off);
    if (lid == 0) red[t >> 5] = l;
    __syncthreads();

    if (t < 32) {
        float v = red[t];
        #pragma unroll
        for (int off = 16; off; off >>= 1) v += __shfl_xor_sync(0xFFFFFFFFu, v, off);
        if (t == 0) out[0] = v / (float)N_OBJ;
    }
}

extern "C" void kernel_launch(void* const* d_in, const int* in_sizes, int n_in,
                              void* d_out, int out_size) {
    // metadata order: det_class_probs (f32), det_mask_probs (f32),
    //                 seg_mask_probs (f32), edge_i (i32), edge_j (i32)
    const float*  dcp = (const float*)d_in[0];
    const float4* det = (const float4*)d_in[1];
    const float4* seg = (const float4*)d_in[2];
    const int*    ei  = (const int*)d_in[3];
    const int*    ej  = (const int*)d_in[4];
    const int n_edges = in_sizes[3] < MAX_EDGES ? in_sizes[3] : MAX_EDGES;
    float* out = (float*)d_out;

    reduce_kernel<<<dim3(NCHUNK, C_DET), RTHREADS>>>(det, seg);
    finalize_kernel<<<1, N_OBJ>>>(dcp, ei, ej, n_edges, out);
}

// round 15
// speedup vs baseline: 1.0240x; 1.0240x over previous
#include <cuda_runtime.h>
#include <math.h>

// Problem constants: N_OBJ=1024, C_DET=8, C_SEG=4, H=W=28
#define C_DET 8
#define C_SEG 4
#define HW4 196          // 28*28/4 (float4 units)
#define N_OBJ 1024
#define NB 8             // objects per block
#define NCHUNK (N_OBJ / NB)   // 128
#define RTHREADS 256
#define MAX_EDGES 64
#define NBLOCKS (NCHUNK * C_DET)  // 1024

// Global double accumulators: [c][0]=denom, [c][1..4]=A[c][s].
// Zero at module load; the tail re-zeroes after reading -> replay-safe.
__device__ double g_acc[C_DET][5];
__device__ unsigned int g_count;   // ticket (acq_rel); reset by last block
__device__ float g_sink;           // DCE-blocker for L2 warm-up

__device__ __forceinline__ unsigned int ticket_acq_rel() {
    unsigned int old;
    asm volatile("atom.add.acq_rel.gpu.global.u32 %0, [%1], 1;"
                 : "=r"(old) : "l"(&g_count) : "memory");
    return old;
}
__device__ __forceinline__ double ld_cg_f64(const double* p) {
    double v;
    asm volatile("ld.global.cg.f64 %0, [%1];" : "=d"(v) : "l"(p));
    return v;
}

// Fused scan + tail. Scan publishes via L2 atomics (no L1 involvement),
// ticket uses release ordering -> NO __threadfence / L1D flush per block
// (the CCTL.IVALL from gpu-scope fences was the R4/R8 fusion overhead).
__global__ __launch_bounds__(RTHREADS) void fused_kernel(
    const float4* __restrict__ det4,   // (N,C_DET,HW4) float4
    const float4* __restrict__ seg4,   // (N,C_DET,C_SEG,HW4) float4
    const float*  __restrict__ dcp,    // (N_OBJ, C_DET)
    const int*    __restrict__ edge_i, // int32
    const int*    __restrict__ edge_j,
    int n_edges,
    float* __restrict__ out)
{
    const int c   = blockIdx.y;
    const int n0  = blockIdx.x * NB;
    const int tid = threadIdx.x;
    const int wid = tid >> 5;
    const int lid = tid & 31;

    // ---------- Scan (R13's best-known loop) ----------
    float dsum = 0.0f;
    float a0 = 0.0f, a1 = 0.0f, a2 = 0.0f, a3 = 0.0f;

    for (int t = tid; t < NB * HW4; t += RTHREADS) {
        const int nl = t / HW4;
        const int q  = t - nl * HW4;
        const size_t m = (size_t)(n0 + nl) * C_DET + c;

        const float4 d = det4[m * HW4 + q];
        dsum += (d.x + d.y) + (d.z + d.w);

        const size_t sb = m * (C_SEG * HW4) + q;
        float4 v;
        v = seg4[sb + 0 * HW4]; a0 += d.x * v.x + d.y * v.y + d.z * v.z + d.w * v.w;
        v = seg4[sb + 1 * HW4]; a1 += d.x * v.x + d.y * v.y + d.z * v.z + d.w * v.w;
        v = seg4[sb + 2 * HW4]; a2 += d.x * v.x + d.y * v.y + d.z * v.z + d.w * v.w;
        v = seg4[sb + 3 * HW4]; a3 += d.x * v.x + d.y * v.y + d.z * v.z + d.w * v.w;
    }

    #pragma unroll
    for (int off = 16; off; off >>= 1) {
        dsum += __shfl_xor_sync(0xFFFFFFFFu, dsum, off);
        a0   += __shfl_xor_sync(0xFFFFFFFFu, a0, off);
        a1   += __shfl_xor_sync(0xFFFFFFFFu, a1, off);
        a2   += __shfl_xor_sync(0xFFFFFFFFu, a2, off);
        a3   += __shfl_xor_sync(0xFFFFFFFFu, a3, off);
    }

    __shared__ float sm[5][RTHREADS / 32];
    if (lid == 0) {
        sm[0][wid] = dsum; sm[1][wid] = a0; sm[2][wid] = a1;
        sm[3][wid] = a2;   sm[4][wid] = a3;
    }
    __syncthreads();

    if (tid < 5) {                      // L2 atomics (bypass L1)
        float r = 0.0f;
        #pragma unroll
        for (int w = 0; w < RTHREADS / 32; w++) r += sm[tid][w];
        atomicAdd(&g_acc[c][tid], (double)r);
    }

    // L2 warm-up for the tail (one block).
    if (blockIdx.x == 0 && c == 0) {
        const float4* dcp4 = (const float4*)dcp;
        float acc2 = 0.0f;
        for (int i = tid; i < N_OBJ * C_DET / 4; i += RTHREADS) {
            const float4 v = __ldcg(dcp4 + i);
            acc2 += v.x + v.y + v.z + v.w;
        }
        if (tid < n_edges)
            acc2 += (float)(__ldcg(edge_i + tid) + __ldcg(edge_j + tid));
        if (tid == 0) g_sink = acc2;
    }

    // ---------- Fence-free ticket ----------
    __shared__ unsigned int s_last;
    if (tid == 0)
        s_last = (ticket_acq_rel() == NBLOCKS - 1) ? 1u : 0u;
    __syncthreads();
    if (!s_last) return;
    if (tid == 0) g_count = 0;          // reset for next graph replay

    // ---------- Tail (last block, 256 threads, L2-warm data) ----------
    __shared__ double s_acc[C_DET][5];
    __shared__ float  s_w[C_DET];
    __shared__ float  s_red[RTHREADS / 32];
    __shared__ int    s_ei[MAX_EDGES], s_ej[MAX_EDGES];

    if (tid < n_edges) { s_ei[tid] = edge_i[tid]; s_ej[tid] = edge_j[tid]; }
    if (tid < C_DET * 5) {
        ((double*)s_acc)[tid] = ld_cg_f64(((const double*)g_acc) + tid);
    }
    __syncthreads();

    // Re-zero accumulators for the next replay (after everyone read them).
    if (tid < C_DET * 5) ((double*)g_acc)[tid] = 0.0;

    // Edge weights (deterministic fixed-order scan, atomic-free).
    if (tid < C_DET) {
        double acc = 0.0;
        for (int e = 0; e < n_edges; e++)
            if (s_ej[e] == tid)
                acc += s_acc[tid][1 + s_ei[e]] / s_acc[tid][0];
        s_w[tid] = (float)acc;
    }
    __syncthreads();

    // Per-object prob + BCE mean (4 objects per thread).
    float w[C_DET];
    #pragma unroll
    for (int k = 0; k < C_DET; k++) w[k] = s_w[k];

    const float4* dcp4 = (const float4*)dcp;
    float l = 0.0f;
    #pragma unroll
    for (int o = 0; o < N_OBJ / RTHREADS; o++) {
        const int obj = o * RTHREADS + tid;
        const float4 d0 = dcp4[obj * 2 + 0];
        const float4 d1 = dcp4[obj * 2 + 1];
        float p = d0.x * w[0] + d0.y * w[1] + d0.z * w[2] + d0.w * w[3]
                + d1.x * w[4] + d1.y * w[5] + d1.z * w[6] + d1.w * w[7];
        l += -fmaxf(logf(p), -100.0f);
    }

    #pragma unroll
    for (int off = 16; off; off >>= 1) l += __shfl_xor_sync(0xFFFFFFFFu, l, off);
    if (lid == 0) s_red[wid] = l;
    __syncthreads();

    if (tid == 0) {
        float v = 0.0f;
        #pragma unroll
        for (int i = 0; i < RTHREADS / 32; i++) v += s_red[i];
        out[0] = v / (float)N_OBJ;
    }
}

extern "C" void kernel_launch(void* const* d_in, const int* in_sizes, int n_in,
                              void* d_out, int out_size) {
    // metadata order: det_class_probs (f32), det_mask_probs (f32),
    //                 seg_mask_probs (f32), edge_i (i32), edge_j (i32)
    const float*  dcp = (const float*)d_in[0];
    const float4* det = (const float4*)d_in[1];
    const float4* seg = (const float4*)d_in[2];
    const int*    ei  = (const int*)d_in[3];
    const int*    ej  = (const int*)d_in[4];
    const int n_edges = in_sizes[3] < MAX_EDGES ? in_sizes[3] : MAX_EDGES;
    float* out = (float*)d_out;

    fused_kernel<<<dim3(NCHUNK, C_DET), RTHREADS>>>(det, seg, dcp, ei, ej, n_edges, out);
}